// round 1
// baseline (speedup 1.0000x reference)
#include <cuda_runtime.h>
#include <math.h>

#define N_MAX 10000
#define E_MAX 160000
#define HD 64
#define NW 8
#define RC_F 4.5f
#define PI_F 3.14159265358979323846f

// ---- device scratch (no allocations allowed) ----
__device__ int   g_cnt[N_MAX];
__device__ int   g_off[N_MAX + 1];
__device__ int   g_perm[E_MAX];
__device__ float g_accI[N_MAX * HD];
__device__ float g_accA[N_MAX * HD * 3];
__device__ float g_accS[N_MAX * HD * 6];
__device__ float g_n0[N_MAX * HD];

// ------------------------------------------------------------------
// Sort edges by src (counting sort)
// ------------------------------------------------------------------
__global__ void k_zero(int n) {
    int i = blockIdx.x * blockDim.x + threadIdx.x;
    if (i < n) g_cnt[i] = 0;
}

__global__ void k_count(const int* __restrict__ ei, int nE) {
    int e = blockIdx.x * blockDim.x + threadIdx.x;
    if (e < nE) atomicAdd(&g_cnt[ei[e]], 1);
}

__global__ void k_scan(int n) {
    __shared__ int part[1024];
    int tid = threadIdx.x;
    const int CH = (N_MAX + 1023) / 1024;  // 10
    int beg = tid * CH;
    int end = beg + CH; if (end > n) end = n;
    int loc[CH];
    int s = 0;
    for (int i = beg; i < end; i++) { loc[i - beg] = s; s += g_cnt[i]; }
    part[tid] = s;
    __syncthreads();
    for (int off = 1; off < 1024; off <<= 1) {
        int t = 0;
        if (tid >= off) t = part[tid - off];
        __syncthreads();
        part[tid] += t;
        __syncthreads();
    }
    int excl = part[tid] - s;
    for (int i = beg; i < end; i++) { g_off[i] = excl + loc[i - beg]; g_cnt[i] = 0; }
    if (tid == 1023) g_off[n] = part[1023];
}

__global__ void k_scatter(const int* __restrict__ ei, int nE) {
    int e = blockIdx.x * blockDim.x + threadIdx.x;
    if (e < nE) {
        int s = ei[e];
        int pos = g_off[s] + atomicAdd(&g_cnt[s], 1);
        g_perm[pos] = e;
    }
}

// ------------------------------------------------------------------
// Edge kernel: one warp per atom; per edge compute Zij, d1..d3 GEMVs,
// accumulate compact (1+3+6) moments per h in registers.
// ------------------------------------------------------------------
__global__ void k_edge(const int* __restrict__ z,
                       const int* __restrict__ ei,
                       const float* __restrict__ ew,
                       const float* __restrict__ evn,
                       const float* __restrict__ attr,
                       const float* __restrict__ emb,
                       const float* __restrict__ e2w,
                       const float* __restrict__ e2b,
                       const float* __restrict__ d1w, const float* __restrict__ d1b,
                       const float* __restrict__ d2w, const float* __restrict__ d2b,
                       const float* __restrict__ d3w, const float* __restrict__ d3b,
                       int n, int nE)
{
    extern __shared__ float sm[];
    float* zW  = sm;                 // [j(128)][h(64)] transposed emb2_w
    float* t1  = zW + 128 * 64;      // [j(64)][h(64)]
    float* t2  = t1 + 64 * 64;
    float* t3  = t2 + 64 * 64;
    float* bz  = t3 + 64 * 64;       // 64
    float* bb1 = bz + 64;
    float* bb2 = bb1 + 64;
    float* bb3 = bb2 + 64;
    float* stage = bb3 + 64;         // NW * 192

    int tid = threadIdx.x;
    for (int i = tid; i < 128 * 64; i += blockDim.x) {
        int j = i >> 6, h = i & 63;
        zW[i] = e2w[h * 128 + j];
    }
    for (int i = tid; i < 64 * 64; i += blockDim.x) {
        int j = i >> 6, h = i & 63;
        t1[i] = d1w[h * 64 + j];
        t2[i] = d2w[h * 64 + j];
        t3[i] = d3w[h * 64 + j];
    }
    for (int i = tid; i < 64; i += blockDim.x) {
        bz[i] = e2b[i]; bb1[i] = d1b[i]; bb2[i] = d2b[i]; bb3[i] = d3b[i];
    }
    __syncthreads();

    int warp = tid >> 5, lane = tid & 31;
    float* st = stage + warp * 192;
    const float2* zW2 = (const float2*)zW;
    const float2* t1v = (const float2*)t1;
    const float2* t2v = (const float2*)t2;
    const float2* t3v = (const float2*)t3;

    for (int atom = blockIdx.x * NW + warp; atom < n; atom += gridDim.x * NW) {
        int e0 = g_off[atom], e1 = g_off[atom + 1];
        float2 aI  = {0.f, 0.f};
        float2 aAx = {0.f, 0.f}, aAy = {0.f, 0.f}, aAz = {0.f, 0.f};
        float2 aSxx = {0.f, 0.f}, aSyy = {0.f, 0.f}, aSzz = {0.f, 0.f};
        float2 aSxy = {0.f, 0.f}, aSxz = {0.f, 0.f}, aSyz = {0.f, 0.f};

        if (e0 < e1) {
            int zi = z[atom];
            st[lane]      = emb[zi * 64 + lane];
            st[lane + 32] = emb[zi * 64 + 32 + lane];
        }
        for (int idx = e0; idx < e1; idx++) {
            int e   = g_perm[idx];
            int dst = ei[nE + e];
            int zj  = z[dst];
            st[64 + lane]  = emb[zj * 64 + lane];
            st[96 + lane]  = emb[zj * 64 + 32 + lane];
            st[128 + lane] = attr[e * 64 + lane];
            st[160 + lane] = attr[e * 64 + 32 + lane];
            __syncwarp();

            float w  = ew[e];
            float C  = (w < RC_F) ? 0.5f * (cosf(w * (PI_F / RC_F)) + 1.0f) : 0.0f;
            float vx = evn[e * 3 + 0], vy = evn[e * 3 + 1], vz = evn[e * 3 + 2];
            float tr3 = (vx * vx + vy * vy + vz * vz) * (1.0f / 3.0f);
            float sxx = vx * vx - tr3, syy = vy * vy - tr3, szz = vz * vz - tr3;
            float sxy = vx * vy, sxz = vx * vz, syz = vy * vz;

            float2 zsum = ((const float2*)bz)[lane];
            float2 s1   = ((const float2*)bb1)[lane];
            float2 s2   = ((const float2*)bb2)[lane];
            float2 s3   = ((const float2*)bb3)[lane];

            #pragma unroll 4
            for (int j = 0; j < 64; j++) {
                float zs = st[j];
                float zd = st[64 + j];
                float aa = st[128 + j];
                float2 wa = zW2[j * 32 + lane];
                float2 wb = zW2[(64 + j) * 32 + lane];
                float2 p1 = t1v[j * 32 + lane];
                float2 p2 = t2v[j * 32 + lane];
                float2 p3 = t3v[j * 32 + lane];
                zsum.x = fmaf(wa.x, zs, zsum.x); zsum.x = fmaf(wb.x, zd, zsum.x);
                zsum.y = fmaf(wa.y, zs, zsum.y); zsum.y = fmaf(wb.y, zd, zsum.y);
                s1.x = fmaf(p1.x, aa, s1.x); s1.y = fmaf(p1.y, aa, s1.y);
                s2.x = fmaf(p2.x, aa, s2.x); s2.y = fmaf(p2.y, aa, s2.y);
                s3.x = fmaf(p3.x, aa, s3.x); s3.y = fmaf(p3.y, aa, s3.y);
            }
            __syncwarp();

            float cz_x = C * zsum.x, cz_y = C * zsum.y;
            float g1x = s1.x * cz_x, g1y = s1.y * cz_y;
            float g2x = s2.x * cz_x, g2y = s2.y * cz_y;
            float g3x = s3.x * cz_x, g3y = s3.y * cz_y;

            aI.x += g1x; aI.y += g1y;
            aAx.x = fmaf(g2x, vx, aAx.x); aAx.y = fmaf(g2y, vx, aAx.y);
            aAy.x = fmaf(g2x, vy, aAy.x); aAy.y = fmaf(g2y, vy, aAy.y);
            aAz.x = fmaf(g2x, vz, aAz.x); aAz.y = fmaf(g2y, vz, aAz.y);
            aSxx.x = fmaf(g3x, sxx, aSxx.x); aSxx.y = fmaf(g3y, sxx, aSxx.y);
            aSyy.x = fmaf(g3x, syy, aSyy.x); aSyy.y = fmaf(g3y, syy, aSyy.y);
            aSzz.x = fmaf(g3x, szz, aSzz.x); aSzz.y = fmaf(g3y, szz, aSzz.y);
            aSxy.x = fmaf(g3x, sxy, aSxy.x); aSxy.y = fmaf(g3y, sxy, aSxy.y);
            aSxz.x = fmaf(g3x, sxz, aSxz.x); aSxz.y = fmaf(g3y, sxz, aSxz.y);
            aSyz.x = fmaf(g3x, syz, aSyz.x); aSyz.y = fmaf(g3y, syz, aSyz.y);
        }

        int base = atom * 64 + lane * 2;
        g_accI[base]     = aI.x;
        g_accI[base + 1] = aI.y;
        int bA = base * 3;
        g_accA[bA + 0] = aAx.x; g_accA[bA + 1] = aAy.x; g_accA[bA + 2] = aAz.x;
        g_accA[bA + 3] = aAx.y; g_accA[bA + 4] = aAy.y; g_accA[bA + 5] = aAz.y;
        int bS = base * 6;
        g_accS[bS + 0] = aSxx.x; g_accS[bS + 1] = aSyy.x; g_accS[bS + 2] = aSzz.x;
        g_accS[bS + 3] = aSxy.x; g_accS[bS + 4] = aSxz.x; g_accS[bS + 5] = aSyz.x;
        g_accS[bS + 6] = aSxx.y; g_accS[bS + 7] = aSyy.y; g_accS[bS + 8] = aSzz.y;
        g_accS[bS + 9] = aSxy.y; g_accS[bS + 10] = aSxz.y; g_accS[bS + 11] = aSyz.y;
    }
}

// ------------------------------------------------------------------
// tn -> layernorm -> MLP -> n0 (only column 0 of the reshape needed)
// ------------------------------------------------------------------
__device__ __forceinline__ float sq(float x) { return x * x; }
__device__ __forceinline__ float silu(float x) { return x / (1.0f + expf(-x)); }

__global__ void k_mlp(const float* __restrict__ lng, const float* __restrict__ lnb,
                      const float* __restrict__ w1, const float* __restrict__ b1,
                      const float* __restrict__ w2, const float* __restrict__ b2,
                      int n)
{
    extern __shared__ float sm[];
    float* w1T  = sm;               // [j(64)][o(128)]
    float* w2nT = w1T + 64 * 128;   // [j(128)][h(64)] rows 3h of w2
    float* sb1  = w2nT + 128 * 64;  // 128
    float* sb2  = sb1 + 128;        // 64 (b2[3h])
    float* slg  = sb2 + 64;
    float* slb  = slg + 64;
    float* wk   = slb + 64;         // NW * 192

    int tid = threadIdx.x;
    for (int i = tid; i < 64 * 128; i += blockDim.x) {
        int j = i >> 7, o = i & 127;
        w1T[i] = w1[o * 64 + j];
    }
    for (int i = tid; i < 128 * 64; i += blockDim.x) {
        int j = i >> 6, h = i & 63;
        w2nT[i] = w2[h * 3 * 128 + j];
    }
    for (int i = tid; i < 128; i += blockDim.x) sb1[i] = b1[i];
    for (int i = tid; i < 64; i += blockDim.x) {
        sb2[i] = b2[3 * i]; slg[i] = lng[i]; slb[i] = lnb[i];
    }
    __syncthreads();

    int warp = tid >> 5, lane = tid & 31;
    float* nm = wk + warp * 192;
    float* h1 = nm + 64;
    const float2* w2n2 = (const float2*)w2nT;

    for (int atom = blockIdx.x * NW + warp; atom < n; atom += gridDim.x * NW) {
        int h0 = lane * 2;
        int base = atom * 64 + h0;
        float i0a = g_accI[base], i0b = g_accI[base + 1];
        const float* A = g_accA + base * 3;
        const float* S = g_accS + base * 6;
        float tna = sq(i0a + S[0]) + sq(i0a + S[1]) + sq(i0a + S[2])
                  + 2.0f * (sq(S[3]) + sq(S[4]) + sq(S[5]) + sq(A[0]) + sq(A[1]) + sq(A[2]));
        float tnb = sq(i0b + S[6]) + sq(i0b + S[7]) + sq(i0b + S[8])
                  + 2.0f * (sq(S[9]) + sq(S[10]) + sq(S[11]) + sq(A[3]) + sq(A[4]) + sq(A[5]));
        float s = tna + tnb;
        for (int o = 16; o; o >>= 1) s += __shfl_xor_sync(0xffffffffu, s, o);
        float mu = s * (1.0f / 64.0f);
        float da = tna - mu, db = tnb - mu;
        float vs = da * da + db * db;
        for (int o = 16; o; o >>= 1) vs += __shfl_xor_sync(0xffffffffu, vs, o);
        float inv = rsqrtf(vs * (1.0f / 64.0f) + 1e-5f);
        nm[h0]     = da * inv * slg[h0] + slb[h0];
        nm[h0 + 1] = db * inv * slg[h0 + 1] + slb[h0 + 1];
        __syncwarp();

        #pragma unroll
        for (int p = 0; p < 4; p++) {
            int o = lane + 32 * p;
            float acc = sb1[o];
            #pragma unroll 8
            for (int j = 0; j < 64; j++) acc = fmaf(w1T[j * 128 + o], nm[j], acc);
            h1[o] = silu(acc);
        }
        __syncwarp();

        float2 acc2 = ((const float2*)sb2)[lane];
        #pragma unroll 8
        for (int j = 0; j < 128; j++) {
            float hv = h1[j];
            float2 wv = w2n2[j * 32 + lane];
            acc2.x = fmaf(wv.x, hv, acc2.x);
            acc2.y = fmaf(wv.y, hv, acc2.y);
        }
        g_n0[base]     = silu(acc2.x);
        g_n0[base + 1] = silu(acc2.y);
        __syncwarp();
    }
}

// ------------------------------------------------------------------
// Final: out[n,k,i,j] = delta_ij * (d1[k] + n0[k]*sum_h d1[h]*(m1+m2)[k,h]),
// d1[k] = n0[k] * sum_h accI[h]*m0[k,h]. Output is diagonal.
// ------------------------------------------------------------------
__global__ void k_final(const float* __restrict__ m0, const float* __restrict__ m1,
                        const float* __restrict__ m2, float* __restrict__ out, int n)
{
    __shared__ float m0T[64 * 64];   // [h][k]
    __shared__ float msT[64 * 64];   // [h][k] of m1+m2
    __shared__ float wk[NW][128];

    int tid = threadIdx.x;
    for (int i = tid; i < 64 * 64; i += blockDim.x) {
        int h = i >> 6, k = i & 63;
        m0T[i] = m0[k * 64 + h];
        msT[i] = m1[k * 64 + h] + m2[k * 64 + h];
    }
    __syncthreads();

    int warp = tid >> 5, lane = tid & 31;
    const float2* m0v = (const float2*)m0T;
    const float2* msv = (const float2*)msT;

    for (int atom = blockIdx.x * NW + warp; atom < n; atom += gridDim.x * NW) {
        int k0 = lane * 2;
        float2 n0v = ((const float2*)(g_n0 + atom * 64))[lane];
        float2 av  = ((const float2*)(g_accI + atom * 64))[lane];
        wk[warp][k0]     = av.x;
        wk[warp][k0 + 1] = av.y;
        __syncwarp();

        float2 d1 = {0.f, 0.f};
        #pragma unroll 8
        for (int h = 0; h < 64; h++) {
            float a = wk[warp][h];
            float2 m = m0v[h * 32 + lane];
            d1.x = fmaf(m.x, a, d1.x);
            d1.y = fmaf(m.y, a, d1.y);
        }
        d1.x *= n0v.x; d1.y *= n0v.y;
        wk[warp][64 + k0]     = d1.x;
        wk[warp][64 + k0 + 1] = d1.y;
        __syncwarp();

        float2 tt = {0.f, 0.f};
        #pragma unroll 8
        for (int h = 0; h < 64; h++) {
            float d = wk[warp][64 + h];
            float2 m = msv[h * 32 + lane];
            tt.x = fmaf(m.x, d, tt.x);
            tt.y = fmaf(m.y, d, tt.y);
        }
        float vx = d1.x + n0v.x * tt.x;
        float vy = d1.y + n0v.y * tt.y;

        // 18 contiguous floats per lane: two diagonal 3x3 matrices
        float2* o = (float2*)(out + (size_t)(atom * 64 + k0) * 9);
        o[0] = make_float2(vx, 0.f);
        o[1] = make_float2(0.f, 0.f);
        o[2] = make_float2(vx, 0.f);
        o[3] = make_float2(0.f, 0.f);
        o[4] = make_float2(vx, vy);
        o[5] = make_float2(0.f, 0.f);
        o[6] = make_float2(0.f, vy);
        o[7] = make_float2(0.f, 0.f);
        o[8] = make_float2(0.f, vy);
        __syncwarp();
    }
}

// ------------------------------------------------------------------
extern "C" void kernel_launch(void* const* d_in, const int* in_sizes, int n_in,
                              void* d_out, int out_size)
{
    const int*   z    = (const int*)d_in[0];
    const int*   ei   = (const int*)d_in[1];
    const float* ew   = (const float*)d_in[2];
    const float* evn  = (const float*)d_in[3];
    const float* attr = (const float*)d_in[4];
    const float* emb  = (const float*)d_in[5];
    const float* e2w  = (const float*)d_in[6];
    const float* e2b  = (const float*)d_in[7];
    const float* d1w  = (const float*)d_in[8];
    const float* d1b  = (const float*)d_in[9];
    const float* d2w  = (const float*)d_in[10];
    const float* d2b  = (const float*)d_in[11];
    const float* d3w  = (const float*)d_in[12];
    const float* d3b  = (const float*)d_in[13];
    const float* lng  = (const float*)d_in[14];
    const float* lnb  = (const float*)d_in[15];
    const float* w1   = (const float*)d_in[16];
    const float* b1   = (const float*)d_in[17];
    const float* w2   = (const float*)d_in[18];
    const float* b2   = (const float*)d_in[19];
    const float* m0   = (const float*)d_in[20];
    const float* m1   = (const float*)d_in[21];
    const float* m2   = (const float*)d_in[22];
    float* out = (float*)d_out;

    int n  = in_sizes[0];
    int nE = in_sizes[2];

    size_t smemE = (size_t)(128 * 64 + 3 * 64 * 64 + 4 * 64 + NW * 192) * sizeof(float);
    size_t smemM = (size_t)(64 * 128 + 128 * 64 + 128 + 3 * 64 + NW * 192) * sizeof(float);
    cudaFuncSetAttribute(k_edge, cudaFuncAttributeMaxDynamicSharedMemorySize, (int)smemE);
    cudaFuncSetAttribute(k_mlp,  cudaFuncAttributeMaxDynamicSharedMemorySize, (int)smemM);

    k_zero<<<(n + 255) / 256, 256>>>(n);
    k_count<<<(nE + 255) / 256, 256>>>(ei, nE);
    k_scan<<<1, 1024>>>(n);
    k_scatter<<<(nE + 255) / 256, 256>>>(ei, nE);

    int ablocks = (n + NW - 1) / NW;
    k_edge<<<ablocks, NW * 32, smemE>>>(z, ei, ew, evn, attr, emb, e2w, e2b,
                                        d1w, d1b, d2w, d2b, d3w, d3b, n, nE);
    k_mlp<<<ablocks, NW * 32, smemM>>>(lng, lnb, w1, b1, w2, b2, n);
    k_final<<<ablocks, NW * 32>>>(m0, m1, m2, out, n);
}

// round 2
// speedup vs baseline: 1.6895x; 1.6895x over previous
#include <cuda_runtime.h>
#include <math.h>

#define N_MAX 10000
#define E_MAX 160000
#define HD 64
#define NW 8
#define NWE 16
#define RC_F 4.5f
#define PI_F 3.14159265358979323846f

typedef unsigned long long ull;

__device__ __forceinline__ ull fma2(ull a, ull b, ull c) {
    ull d; asm("fma.rn.f32x2 %0,%1,%2,%3;" : "=l"(d) : "l"(a), "l"(b), "l"(c)); return d;
}
__device__ __forceinline__ ull mul2(ull a, ull b) {
    ull d; asm("mul.rn.f32x2 %0,%1,%2;" : "=l"(d) : "l"(a), "l"(b)); return d;
}
__device__ __forceinline__ ull add2(ull a, ull b) {
    ull d; asm("add.rn.f32x2 %0,%1,%2;" : "=l"(d) : "l"(a), "l"(b)); return d;
}
__device__ __forceinline__ ull packdup(float x) {
    ull d; asm("mov.b64 %0,{%1,%1};" : "=l"(d) : "f"(x)); return d;
}
__device__ __forceinline__ float2 unpack2(ull a) {
    float2 v; asm("mov.b64 {%0,%1},%2;" : "=f"(v.x), "=f"(v.y) : "l"(a)); return v;
}

// ---- device scratch ----
__device__ int   g_cnt[N_MAX];
__device__ int   g_off[N_MAX + 1];
__device__ int   g_perm[E_MAX];
__device__ float g_accI[N_MAX * HD];
__device__ float g_accA[N_MAX * HD * 3];
__device__ float g_accS[N_MAX * HD * 6];
__device__ float g_n0[N_MAX * HD];

// ------------------------------------------------------------------
// Counting sort of edges by src
// ------------------------------------------------------------------
__global__ void k_zero(int n) {
    int i = blockIdx.x * blockDim.x + threadIdx.x;
    if (i < n) g_cnt[i] = 0;
}

__global__ void k_count(const int* __restrict__ ei, int nE) {
    int e = blockIdx.x * blockDim.x + threadIdx.x;
    if (e < nE) atomicAdd(&g_cnt[ei[e]], 1);
}

__global__ void k_scan(int n) {
    __shared__ int part[1024];
    int tid = threadIdx.x;
    const int CH = (N_MAX + 1023) / 1024;
    int beg = tid * CH;
    int end = beg + CH; if (end > n) end = n;
    int loc[CH];
    int s = 0;
    for (int i = beg; i < end; i++) { loc[i - beg] = s; s += g_cnt[i]; }
    part[tid] = s;
    __syncthreads();
    for (int off = 1; off < 1024; off <<= 1) {
        int t = 0;
        if (tid >= off) t = part[tid - off];
        __syncthreads();
        part[tid] += t;
        __syncthreads();
    }
    int excl = part[tid] - s;
    for (int i = beg; i < end; i++) { g_off[i] = excl + loc[i - beg]; g_cnt[i] = 0; }
    if (tid == 1023) g_off[n] = part[1023];
}

__global__ void k_scatter(const int* __restrict__ ei, int nE) {
    int e = blockIdx.x * blockDim.x + threadIdx.x;
    if (e < nE) {
        int s = ei[e];
        int pos = g_off[s] + atomicAdd(&g_cnt[s], 1);
        g_perm[pos] = e;
    }
}

// ------------------------------------------------------------------
// Edge kernel: warp per atom, 4-edge batches, f32x2 packed math.
// ------------------------------------------------------------------
__global__ __launch_bounds__(NWE * 32, 1)
void k_edge(const int* __restrict__ z,
            const int* __restrict__ ei,
            const float* __restrict__ ew,
            const float* __restrict__ evn,
            const float* __restrict__ attr,
            const float* __restrict__ emb,
            const float* __restrict__ e2w,
            const float* __restrict__ e2b,
            const float* __restrict__ d1w, const float* __restrict__ d1b,
            const float* __restrict__ d2w, const float* __restrict__ d2b,
            const float* __restrict__ d3w, const float* __restrict__ d3b,
            int n, int nE)
{
    extern __shared__ float sm[];
    float* zW  = sm;                 // [j(128)][h(64)]
    float* t1  = zW + 128 * 64;
    float* t2  = t1 + 64 * 64;
    float* t3  = t2 + 64 * 64;
    float* bz  = t3 + 64 * 64;
    float* bb1 = bz + 64;
    float* bb2 = bb1 + 64;
    float* bb3 = bb2 + 64;
    float* stage = bb3 + 64;         // NWE * 688

    int tid = threadIdx.x;
    for (int i = tid; i < 128 * 64; i += blockDim.x) {
        int j = i >> 6, h = i & 63;
        zW[i] = e2w[h * 128 + j];
    }
    for (int i = tid; i < 64 * 64; i += blockDim.x) {
        int j = i >> 6, h = i & 63;
        t1[i] = d1w[h * 64 + j];
        t2[i] = d2w[h * 64 + j];
        t3[i] = d3w[h * 64 + j];
    }
    for (int i = tid; i < 64; i += blockDim.x) {
        bz[i] = e2b[i]; bb1[i] = d1b[i]; bb2[i] = d2b[i]; bb3[i] = d3b[i];
    }
    __syncthreads();

    int warp = tid >> 5, lane = tid & 31;
    float* wst   = stage + warp * 688;
    float* combo = wst;              // 4 * 128 floats, interleaved (zd, aa) pairs
    float* zsd   = wst + 512;        // 128 floats, (zs, zs) pairs
    float* meta  = wst + 640;        // 4 * 12

    const ull* zWu = (const ull*)zW;   // index [j*32 + lane]
    const ull* t1u = (const ull*)t1;
    const ull* t2u = (const ull*)t2;
    const ull* t3u = (const ull*)t3;
    const ull* zsdU = (const ull*)zsd;
    const float2* comboF = (const float2*)combo;   // [b*64 + j]

    for (int atom = blockIdx.x * NWE + warp; atom < n; atom += gridDim.x * NWE) {
        int e0 = g_off[atom], e1 = g_off[atom + 1];

        ull aI = 0ull;
        ull aAx = 0ull, aAy = 0ull, aAz = 0ull;
        ull aSxx = 0ull, aSyy = 0ull, aSzz = 0ull;
        ull aSxy = 0ull, aSxz = 0ull, aSyz = 0ull;

        if (e0 < e1) {
            int zi = z[atom];
            float2 zsv = ((const float2*)(emb + (size_t)zi * 64))[lane];
            ((float2*)zsd)[2 * lane]     = make_float2(zsv.x, zsv.x);
            ((float2*)zsd)[2 * lane + 1] = make_float2(zsv.y, zsv.y);
            __syncwarp();

            // per-atom part of Zij: bias + sum_j wa[j] * zs[j]
            ull zS = ((const ull*)bz)[lane];
            #pragma unroll 8
            for (int j = 0; j < 64; j++)
                zS = fma2(zWu[j * 32 + lane], zsdU[j], zS);

            ull bias1 = ((const ull*)bb1)[lane];
            ull bias2 = ((const ull*)bb2)[lane];
            ull bias3 = ((const ull*)bb3)[lane];

            for (int idx = e0; idx < e1; idx += 4) {
                int nb = e1 - idx; if (nb > 4) nb = 4;
                int i1 = idx + 1 < e1 ? idx + 1 : e1 - 1;
                int i2 = idx + 2 < e1 ? idx + 2 : e1 - 1;
                int i3 = idx + 3 < e1 ? idx + 3 : e1 - 1;
                int ea = g_perm[idx], ebx = g_perm[i1], ec = g_perm[i2], ed = g_perm[i3];
                int d0 = ei[nE + ea], d1_ = ei[nE + ebx], d2_ = ei[nE + ec], d3_ = ei[nE + ed];
                int z0 = z[d0], z1 = z[d1_], z2 = z[d2_], z3 = z[d3_];

                float2 e0v = ((const float2*)(emb + (size_t)z0 * 64))[lane];
                float2 e1v = ((const float2*)(emb + (size_t)z1 * 64))[lane];
                float2 e2v = ((const float2*)(emb + (size_t)z2 * 64))[lane];
                float2 e3v = ((const float2*)(emb + (size_t)z3 * 64))[lane];
                float2 a0v = ((const float2*)(attr + (size_t)ea * 64))[lane];
                float2 a1v = ((const float2*)(attr + (size_t)ebx * 64))[lane];
                float2 a2v = ((const float2*)(attr + (size_t)ec * 64))[lane];
                float2 a3v = ((const float2*)(attr + (size_t)ed * 64))[lane];

                float2* cf = (float2*)combo;
                cf[0 * 64 + 2 * lane]     = make_float2(e0v.x, a0v.x);
                cf[0 * 64 + 2 * lane + 1] = make_float2(e0v.y, a0v.y);
                cf[1 * 64 + 2 * lane]     = make_float2(e1v.x, a1v.x);
                cf[1 * 64 + 2 * lane + 1] = make_float2(e1v.y, a1v.y);
                cf[2 * 64 + 2 * lane]     = make_float2(e2v.x, a2v.x);
                cf[2 * 64 + 2 * lane + 1] = make_float2(e2v.y, a2v.y);
                cf[3 * 64 + 2 * lane]     = make_float2(e3v.x, a3v.x);
                cf[3 * 64 + 2 * lane + 1] = make_float2(e3v.y, a3v.y);

                if (lane < 4) {
                    int ii = idx + lane < e1 ? idx + lane : e1 - 1;
                    int e = g_perm[ii];
                    float w = ew[e];
                    float C = (w < RC_F) ? 0.5f * (cosf(w * (PI_F / RC_F)) + 1.0f) : 0.0f;
                    float vx = evn[e * 3 + 0], vy = evn[e * 3 + 1], vz = evn[e * 3 + 2];
                    float tr3 = (vx * vx + vy * vy + vz * vz) * (1.0f / 3.0f);
                    float* mp = meta + lane * 12;
                    mp[0] = C; mp[1] = vx; mp[2] = vy; mp[3] = vz;
                    mp[4] = vx * vx - tr3; mp[5] = vy * vy - tr3; mp[6] = vz * vz - tr3;
                    mp[7] = vx * vy; mp[8] = vx * vz; mp[9] = vy * vz;
                }
                __syncwarp();

                ull zq0 = zS, zq1 = zS, zq2 = zS, zq3 = zS;
                ull s10 = bias1, s11 = bias1, s12 = bias1, s13 = bias1;
                ull s20 = bias2, s21 = bias2, s22 = bias2, s23 = bias2;
                ull s30 = bias3, s31 = bias3, s32 = bias3, s33 = bias3;

                #pragma unroll 4
                for (int j = 0; j < 64; j++) {
                    ull wb = zWu[(64 + j) * 32 + lane];
                    ull p1 = t1u[j * 32 + lane];
                    ull p2 = t2u[j * 32 + lane];
                    ull p3 = t3u[j * 32 + lane];

                    float2 c0 = comboF[0 * 64 + j];
                    ull zd2 = packdup(c0.x), aa2 = packdup(c0.y);
                    zq0 = fma2(wb, zd2, zq0);
                    s10 = fma2(p1, aa2, s10); s20 = fma2(p2, aa2, s20); s30 = fma2(p3, aa2, s30);

                    float2 c1 = comboF[1 * 64 + j];
                    zd2 = packdup(c1.x); aa2 = packdup(c1.y);
                    zq1 = fma2(wb, zd2, zq1);
                    s11 = fma2(p1, aa2, s11); s21 = fma2(p2, aa2, s21); s31 = fma2(p3, aa2, s31);

                    float2 c2 = comboF[2 * 64 + j];
                    zd2 = packdup(c2.x); aa2 = packdup(c2.y);
                    zq2 = fma2(wb, zd2, zq2);
                    s12 = fma2(p1, aa2, s12); s22 = fma2(p2, aa2, s22); s32 = fma2(p3, aa2, s32);

                    float2 c3 = comboF[3 * 64 + j];
                    zd2 = packdup(c3.x); aa2 = packdup(c3.y);
                    zq3 = fma2(wb, zd2, zq3);
                    s13 = fma2(p1, aa2, s13); s23 = fma2(p2, aa2, s23); s33 = fma2(p3, aa2, s33);
                }

                #pragma unroll
                for (int b = 0; b < 4; b++) {
                    if (b >= nb) break;
                    ull zq = (b == 0) ? zq0 : (b == 1) ? zq1 : (b == 2) ? zq2 : zq3;
                    ull s1 = (b == 0) ? s10 : (b == 1) ? s11 : (b == 2) ? s12 : s13;
                    ull s2 = (b == 0) ? s20 : (b == 1) ? s21 : (b == 2) ? s22 : s23;
                    ull s3 = (b == 0) ? s30 : (b == 1) ? s31 : (b == 2) ? s32 : s33;
                    const float* mp = meta + b * 12;
                    ull cz = mul2(packdup(mp[0]), zq);
                    ull g1 = mul2(s1, cz);
                    ull g2 = mul2(s2, cz);
                    ull g3 = mul2(s3, cz);
                    aI  = add2(aI, g1);
                    aAx = fma2(g2, packdup(mp[1]), aAx);
                    aAy = fma2(g2, packdup(mp[2]), aAy);
                    aAz = fma2(g2, packdup(mp[3]), aAz);
                    aSxx = fma2(g3, packdup(mp[4]), aSxx);
                    aSyy = fma2(g3, packdup(mp[5]), aSyy);
                    aSzz = fma2(g3, packdup(mp[6]), aSzz);
                    aSxy = fma2(g3, packdup(mp[7]), aSxy);
                    aSxz = fma2(g3, packdup(mp[8]), aSxz);
                    aSyz = fma2(g3, packdup(mp[9]), aSyz);
                }
                __syncwarp();
            }
        }

        int base = atom * 64 + lane * 2;
        float2 vI = unpack2(aI);
        g_accI[base] = vI.x; g_accI[base + 1] = vI.y;
        float2 vAx = unpack2(aAx), vAy = unpack2(aAy), vAz = unpack2(aAz);
        int bA = base * 3;
        g_accA[bA + 0] = vAx.x; g_accA[bA + 1] = vAy.x; g_accA[bA + 2] = vAz.x;
        g_accA[bA + 3] = vAx.y; g_accA[bA + 4] = vAy.y; g_accA[bA + 5] = vAz.y;
        float2 vSxx = unpack2(aSxx), vSyy = unpack2(aSyy), vSzz = unpack2(aSzz);
        float2 vSxy = unpack2(aSxy), vSxz = unpack2(aSxz), vSyz = unpack2(aSyz);
        int bS = base * 6;
        g_accS[bS + 0] = vSxx.x; g_accS[bS + 1] = vSyy.x; g_accS[bS + 2] = vSzz.x;
        g_accS[bS + 3] = vSxy.x; g_accS[bS + 4] = vSxz.x; g_accS[bS + 5] = vSyz.x;
        g_accS[bS + 6] = vSxx.y; g_accS[bS + 7] = vSyy.y; g_accS[bS + 8] = vSzz.y;
        g_accS[bS + 9] = vSxy.y; g_accS[bS + 10] = vSxz.y; g_accS[bS + 11] = vSyz.y;
    }
}

// ------------------------------------------------------------------
// tn -> layernorm -> MLP -> n0
// ------------------------------------------------------------------
__device__ __forceinline__ float sq(float x) { return x * x; }
__device__ __forceinline__ float silu(float x) { return x / (1.0f + expf(-x)); }

__global__ void k_mlp(const float* __restrict__ lng, const float* __restrict__ lnb,
                      const float* __restrict__ w1, const float* __restrict__ b1,
                      const float* __restrict__ w2, const float* __restrict__ b2,
                      int n)
{
    extern __shared__ float sm[];
    float* w1T  = sm;               // [j(64)][o(128)]
    float* w2nT = w1T + 64 * 128;   // [j(128)][h(64)]
    float* sb1  = w2nT + 128 * 64;
    float* sb2  = sb1 + 128;
    float* slg  = sb2 + 64;
    float* slb  = slg + 64;
    float* wk   = slb + 64;         // NW * 192

    int tid = threadIdx.x;
    for (int i = tid; i < 64 * 128; i += blockDim.x) {
        int j = i >> 7, o = i & 127;
        w1T[i] = w1[o * 64 + j];
    }
    for (int i = tid; i < 128 * 64; i += blockDim.x) {
        int j = i >> 6, h = i & 63;
        w2nT[i] = w2[h * 3 * 128 + j];
    }
    for (int i = tid; i < 128; i += blockDim.x) sb1[i] = b1[i];
    for (int i = tid; i < 64; i += blockDim.x) {
        sb2[i] = b2[3 * i]; slg[i] = lng[i]; slb[i] = lnb[i];
    }
    __syncthreads();

    int warp = tid >> 5, lane = tid & 31;
    float* nm = wk + warp * 192;
    float* h1 = nm + 64;
    const float2* w2n2 = (const float2*)w2nT;

    for (int atom = blockIdx.x * NW + warp; atom < n; atom += gridDim.x * NW) {
        int h0 = lane * 2;
        int base = atom * 64 + h0;
        float i0a = g_accI[base], i0b = g_accI[base + 1];
        const float* A = g_accA + base * 3;
        const float* S = g_accS + base * 6;
        float tna = sq(i0a + S[0]) + sq(i0a + S[1]) + sq(i0a + S[2])
                  + 2.0f * (sq(S[3]) + sq(S[4]) + sq(S[5]) + sq(A[0]) + sq(A[1]) + sq(A[2]));
        float tnb = sq(i0b + S[6]) + sq(i0b + S[7]) + sq(i0b + S[8])
                  + 2.0f * (sq(S[9]) + sq(S[10]) + sq(S[11]) + sq(A[3]) + sq(A[4]) + sq(A[5]));
        float s = tna + tnb;
        for (int o = 16; o; o >>= 1) s += __shfl_xor_sync(0xffffffffu, s, o);
        float mu = s * (1.0f / 64.0f);
        float da = tna - mu, db = tnb - mu;
        float vs = da * da + db * db;
        for (int o = 16; o; o >>= 1) vs += __shfl_xor_sync(0xffffffffu, vs, o);
        float inv = rsqrtf(vs * (1.0f / 64.0f) + 1e-5f);
        nm[h0]     = da * inv * slg[h0] + slb[h0];
        nm[h0 + 1] = db * inv * slg[h0 + 1] + slb[h0 + 1];
        __syncwarp();

        #pragma unroll
        for (int p = 0; p < 4; p++) {
            int o = lane + 32 * p;
            float acc = sb1[o];
            #pragma unroll 8
            for (int j = 0; j < 64; j++) acc = fmaf(w1T[j * 128 + o], nm[j], acc);
            h1[o] = silu(acc);
        }
        __syncwarp();

        float2 acc2 = ((const float2*)sb2)[lane];
        #pragma unroll 8
        for (int j = 0; j < 128; j++) {
            float hv = h1[j];
            float2 wv = w2n2[j * 32 + lane];
            acc2.x = fmaf(wv.x, hv, acc2.x);
            acc2.y = fmaf(wv.y, hv, acc2.y);
        }
        g_n0[base]     = silu(acc2.x);
        g_n0[base + 1] = silu(acc2.y);
        __syncwarp();
    }
}

// ------------------------------------------------------------------
// Final diagonal output
// ------------------------------------------------------------------
__global__ void k_final(const float* __restrict__ m0, const float* __restrict__ m1,
                        const float* __restrict__ m2, float* __restrict__ out, int n)
{
    __shared__ float m0T[64 * 64];
    __shared__ float msT[64 * 64];
    __shared__ float wk[NW][128];

    int tid = threadIdx.x;
    for (int i = tid; i < 64 * 64; i += blockDim.x) {
        int h = i >> 6, k = i & 63;
        m0T[i] = m0[k * 64 + h];
        msT[i] = m1[k * 64 + h] + m2[k * 64 + h];
    }
    __syncthreads();

    int warp = tid >> 5, lane = tid & 31;
    const float2* m0v = (const float2*)m0T;
    const float2* msv = (const float2*)msT;

    for (int atom = blockIdx.x * NW + warp; atom < n; atom += gridDim.x * NW) {
        int k0 = lane * 2;
        float2 n0v = ((const float2*)(g_n0 + atom * 64))[lane];
        float2 av  = ((const float2*)(g_accI + atom * 64))[lane];
        wk[warp][k0]     = av.x;
        wk[warp][k0 + 1] = av.y;
        __syncwarp();

        float2 d1 = {0.f, 0.f};
        #pragma unroll 8
        for (int h = 0; h < 64; h++) {
            float a = wk[warp][h];
            float2 m = m0v[h * 32 + lane];
            d1.x = fmaf(m.x, a, d1.x);
            d1.y = fmaf(m.y, a, d1.y);
        }
        d1.x *= n0v.x; d1.y *= n0v.y;
        wk[warp][64 + k0]     = d1.x;
        wk[warp][64 + k0 + 1] = d1.y;
        __syncwarp();

        float2 tt = {0.f, 0.f};
        #pragma unroll 8
        for (int h = 0; h < 64; h++) {
            float d = wk[warp][64 + h];
            float2 m = msv[h * 32 + lane];
            tt.x = fmaf(m.x, d, tt.x);
            tt.y = fmaf(m.y, d, tt.y);
        }
        float vx = d1.x + n0v.x * tt.x;
        float vy = d1.y + n0v.y * tt.y;

        float2* o = (float2*)(out + (size_t)(atom * 64 + k0) * 9);
        o[0] = make_float2(vx, 0.f);
        o[1] = make_float2(0.f, 0.f);
        o[2] = make_float2(vx, 0.f);
        o[3] = make_float2(0.f, 0.f);
        o[4] = make_float2(vx, vy);
        o[5] = make_float2(0.f, 0.f);
        o[6] = make_float2(0.f, vy);
        o[7] = make_float2(0.f, 0.f);
        o[8] = make_float2(0.f, vy);
        __syncwarp();
    }
}

// ------------------------------------------------------------------
extern "C" void kernel_launch(void* const* d_in, const int* in_sizes, int n_in,
                              void* d_out, int out_size)
{
    const int*   z    = (const int*)d_in[0];
    const int*   ei   = (const int*)d_in[1];
    const float* ew   = (const float*)d_in[2];
    const float* evn  = (const float*)d_in[3];
    const float* attr = (const float*)d_in[4];
    const float* emb  = (const float*)d_in[5];
    const float* e2w  = (const float*)d_in[6];
    const float* e2b  = (const float*)d_in[7];
    const float* d1w  = (const float*)d_in[8];
    const float* d1b  = (const float*)d_in[9];
    const float* d2w  = (const float*)d_in[10];
    const float* d2b  = (const float*)d_in[11];
    const float* d3w  = (const float*)d_in[12];
    const float* d3b  = (const float*)d_in[13];
    const float* lng  = (const float*)d_in[14];
    const float* lnb  = (const float*)d_in[15];
    const float* w1   = (const float*)d_in[16];
    const float* b1   = (const float*)d_in[17];
    const float* w2   = (const float*)d_in[18];
    const float* b2   = (const float*)d_in[19];
    const float* m0   = (const float*)d_in[20];
    const float* m1   = (const float*)d_in[21];
    const float* m2   = (const float*)d_in[22];
    float* out = (float*)d_out;

    int n  = in_sizes[0];
    int nE = in_sizes[2];

    size_t smemE = (size_t)(128 * 64 + 3 * 64 * 64 + 4 * 64 + NWE * 688) * sizeof(float);
    size_t smemM = (size_t)(64 * 128 + 128 * 64 + 128 + 3 * 64 + NW * 192) * sizeof(float);
    cudaFuncSetAttribute(k_edge, cudaFuncAttributeMaxDynamicSharedMemorySize, (int)smemE);
    cudaFuncSetAttribute(k_mlp,  cudaFuncAttributeMaxDynamicSharedMemorySize, (int)smemM);

    k_zero<<<(n + 255) / 256, 256>>>(n);
    k_count<<<(nE + 255) / 256, 256>>>(ei, nE);
    k_scan<<<1, 1024>>>(n);
    k_scatter<<<(nE + 255) / 256, 256>>>(ei, nE);

    int eblocks = (n + NWE - 1) / NWE;
    k_edge<<<eblocks, NWE * 32, smemE>>>(z, ei, ew, evn, attr, emb, e2w, e2b,
                                         d1w, d1b, d2w, d2b, d3w, d3b, n, nE);
    int ablocks = (n + NW - 1) / NW;
    k_mlp<<<ablocks, NW * 32, smemM>>>(lng, lnb, w1, b1, w2, b2, n);
    k_final<<<ablocks, NW * 32>>>(m0, m1, m2, out, n);
}

// round 3
// speedup vs baseline: 2.2358x; 1.3234x over previous
#include <cuda_runtime.h>
#include <math.h>

#define N_MAX 10000
#define E_MAX 160000
#define HD 64
#define NW 8
#define NWE 16
#define RC_F 4.5f
#define PI_F 3.14159265358979323846f

typedef unsigned long long ull;

__device__ __forceinline__ ull fma2(ull a, ull b, ull c) {
    ull d; asm("fma.rn.f32x2 %0,%1,%2,%3;" : "=l"(d) : "l"(a), "l"(b), "l"(c)); return d;
}
__device__ __forceinline__ ull mul2(ull a, ull b) {
    ull d; asm("mul.rn.f32x2 %0,%1,%2;" : "=l"(d) : "l"(a), "l"(b)); return d;
}
__device__ __forceinline__ ull add2(ull a, ull b) {
    ull d; asm("add.rn.f32x2 %0,%1,%2;" : "=l"(d) : "l"(a), "l"(b)); return d;
}
__device__ __forceinline__ ull pack2(float x, float y) {
    ull d; asm("mov.b64 %0,{%1,%2};" : "=l"(d) : "f"(x), "f"(y)); return d;
}
__device__ __forceinline__ float2 unpack2(ull a) {
    float2 v; asm("mov.b64 {%0,%1},%2;" : "=f"(v.x), "=f"(v.y) : "l"(a)); return v;
}

// ---- device scratch ----
__device__ int   g_cnt[N_MAX];
__device__ int   g_off[N_MAX + 1];
__device__ int   g_perm[E_MAX];
__device__ int   g_ctr;
__device__ float g_ZS[256 * 64];
__device__ float g_ZD[256 * 64];
__device__ float g_accI[N_MAX * HD];
__device__ float g_accA[N_MAX * HD * 3];
__device__ float g_accS[N_MAX * HD * 6];
__device__ float g_n0[N_MAX * HD];

// ------------------------------------------------------------------
// Counting sort of edges by src
// ------------------------------------------------------------------
__global__ void k_zero(int n) {
    int i = blockIdx.x * blockDim.x + threadIdx.x;
    if (i == 0) g_ctr = 0;
    if (i < n) g_cnt[i] = 0;
}

__global__ void k_count(const int* __restrict__ ei, int nE) {
    int e = blockIdx.x * blockDim.x + threadIdx.x;
    if (e < nE) atomicAdd(&g_cnt[ei[e]], 1);
}

__global__ void k_scan(int n) {
    __shared__ int part[1024];
    int tid = threadIdx.x;
    const int CH = (N_MAX + 1023) / 1024;
    int beg = tid * CH;
    int end = beg + CH; if (end > n) end = n;
    int loc[CH];
    int s = 0;
    for (int i = beg; i < end; i++) { loc[i - beg] = s; s += g_cnt[i]; }
    part[tid] = s;
    __syncthreads();
    for (int off = 1; off < 1024; off <<= 1) {
        int t = 0;
        if (tid >= off) t = part[tid - off];
        __syncthreads();
        part[tid] += t;
        __syncthreads();
    }
    int excl = part[tid] - s;
    for (int i = beg; i < end; i++) { g_off[i] = excl + loc[i - beg]; g_cnt[i] = 0; }
    if (tid == 1023) g_off[n] = part[1023];
}

__global__ void k_scatter(const int* __restrict__ ei, int nE) {
    int e = blockIdx.x * blockDim.x + threadIdx.x;
    if (e < nE) {
        int s = ei[e];
        int pos = g_off[s] + atomicAdd(&g_cnt[s], 1);
        g_perm[pos] = e;
    }
}

// ------------------------------------------------------------------
// Precompute ZS[z,h] = emb2_b[h] + sum_j e2w[h,j] emb[z,j]
//            ZD[z,h] =            sum_j e2w[h,64+j] emb[z,j]
// ------------------------------------------------------------------
__global__ void k_pre(const float* __restrict__ emb, const float* __restrict__ e2w,
                      const float* __restrict__ e2b) {
    int zz = blockIdx.x;
    int h = threadIdx.x;
    __shared__ float er[64];
    er[h] = emb[zz * 64 + h];
    __syncthreads();
    float ss = e2b[h], sd = 0.f;
    #pragma unroll 8
    for (int j = 0; j < 64; j++) {
        ss = fmaf(e2w[h * 128 + j], er[j], ss);
        sd = fmaf(e2w[h * 128 + 64 + j], er[j], sd);
    }
    g_ZS[zz * 64 + h] = ss;
    g_ZD[zz * 64 + h] = sd;
}

// ------------------------------------------------------------------
// Edge kernel
// ------------------------------------------------------------------
struct Acc {
    ull I, Ax, Ay, Az, Sxx, Syy, Szz, Sxy, Sxz, Syz;
};

template<int NB>
__device__ __forceinline__ void do_batch(
    int idx, int e1, int nb, int lane,
    const int* __restrict__ ei, int nE,
    const int* __restrict__ z,
    const float* __restrict__ ew,
    const float* __restrict__ evn,
    const float* __restrict__ attr,
    const ull* __restrict__ t1u, const ull* __restrict__ t2u, const ull* __restrict__ t3u,
    ull bias1, ull bias2, ull bias3, ull zS2,
    ull* att2, float* meta, Acc& A)
{
    int eidx[NB], zj[NB];
    #pragma unroll
    for (int b = 0; b < NB; b++) {
        int ii = idx + b; if (ii >= e1) ii = e1 - 1;
        eidx[b] = g_perm[ii];
    }
    #pragma unroll
    for (int b = 0; b < NB; b++) zj[b] = z[ei[nE + eidx[b]]];
    ull zd[NB];
    #pragma unroll
    for (int b = 0; b < NB; b++)
        zd[b] = ((const ull*)g_ZD)[zj[b] * 32 + lane];

    #pragma unroll
    for (int b = 0; b < NB; b++) {
        float2 v = ((const float2*)(attr + (size_t)eidx[b] * 64))[lane];
        att2[b * 64 + 2 * lane]     = pack2(v.x, v.x);
        att2[b * 64 + 2 * lane + 1] = pack2(v.y, v.y);
    }
    if (lane < NB) {
        int e = eidx[lane];
        float w = ew[e];
        float C = (w < RC_F) ? 0.5f * (cosf(w * (PI_F / RC_F)) + 1.0f) : 0.0f;
        float vx = evn[e * 3 + 0], vy = evn[e * 3 + 1], vz = evn[e * 3 + 2];
        float tr3 = (vx * vx + vy * vy + vz * vz) * (1.0f / 3.0f);
        float2* mp = (float2*)(meta + lane * 20);
        mp[0] = make_float2(C, C);
        mp[1] = make_float2(vx, vx);
        mp[2] = make_float2(vy, vy);
        mp[3] = make_float2(vz, vz);
        mp[4] = make_float2(vx * vx - tr3, vx * vx - tr3);
        mp[5] = make_float2(vy * vy - tr3, vy * vy - tr3);
        mp[6] = make_float2(vz * vz - tr3, vz * vz - tr3);
        mp[7] = make_float2(vx * vy, vx * vy);
        mp[8] = make_float2(vx * vz, vx * vz);
        mp[9] = make_float2(vy * vz, vy * vz);
    }
    __syncwarp();

    ull s1[NB], s2[NB], s3[NB];
    #pragma unroll
    for (int b = 0; b < NB; b++) { s1[b] = bias1; s2[b] = bias2; s3[b] = bias3; }

    #pragma unroll 4
    for (int j = 0; j < 64; j++) {
        ull p1 = t1u[j * 32 + lane];
        ull p2 = t2u[j * 32 + lane];
        ull p3 = t3u[j * 32 + lane];
        #pragma unroll
        for (int b = 0; b < NB; b++) {
            ull aa = att2[b * 64 + j];
            s1[b] = fma2(p1, aa, s1[b]);
            s2[b] = fma2(p2, aa, s2[b]);
            s3[b] = fma2(p3, aa, s3[b]);
        }
    }

    #pragma unroll
    for (int b = 0; b < NB; b++) {
        if (b >= nb) break;
        const ull* mp = (const ull*)(meta + b * 20);
        ull zfac = mul2(mp[0], add2(zS2, zd[b]));
        ull g1 = mul2(s1[b], zfac);
        ull g2 = mul2(s2[b], zfac);
        ull g3 = mul2(s3[b], zfac);
        A.I   = add2(A.I, g1);
        A.Ax  = fma2(g2, mp[1], A.Ax);
        A.Ay  = fma2(g2, mp[2], A.Ay);
        A.Az  = fma2(g2, mp[3], A.Az);
        A.Sxx = fma2(g3, mp[4], A.Sxx);
        A.Syy = fma2(g3, mp[5], A.Syy);
        A.Szz = fma2(g3, mp[6], A.Szz);
        A.Sxy = fma2(g3, mp[7], A.Sxy);
        A.Sxz = fma2(g3, mp[8], A.Sxz);
        A.Syz = fma2(g3, mp[9], A.Syz);
    }
    __syncwarp();
}

__global__ __launch_bounds__(NWE * 32, 1)
void k_edge(const int* __restrict__ z,
            const int* __restrict__ ei,
            const float* __restrict__ ew,
            const float* __restrict__ evn,
            const float* __restrict__ attr,
            const float* __restrict__ d1w, const float* __restrict__ d1b,
            const float* __restrict__ d2w, const float* __restrict__ d2b,
            const float* __restrict__ d3w, const float* __restrict__ d3b,
            int n, int nE)
{
    extern __shared__ float sm[];
    float* t1  = sm;                 // [j(64)][h(64)]
    float* t2  = t1 + 64 * 64;
    float* t3  = t2 + 64 * 64;
    float* bb1 = t3 + 64 * 64;
    float* bb2 = bb1 + 64;
    float* bb3 = bb2 + 64;
    float* stage = bb3 + 64;         // NWE * 1184 floats

    int tid = threadIdx.x;
    for (int i = tid; i < 64 * 64; i += blockDim.x) {
        int j = i >> 6, h = i & 63;
        t1[i] = d1w[h * 64 + j];
        t2[i] = d2w[h * 64 + j];
        t3[i] = d3w[h * 64 + j];
    }
    for (int i = tid; i < 64; i += blockDim.x) {
        bb1[i] = d1b[i]; bb2[i] = d2b[i]; bb3[i] = d3b[i];
    }
    __syncthreads();

    int warp = tid >> 5, lane = tid & 31;
    float* wst = stage + warp * 1184;
    ull*   att2 = (ull*)wst;         // 512 ull
    float* meta = wst + 1024;        // 160 floats

    const ull* t1u = (const ull*)t1;
    const ull* t2u = (const ull*)t2;
    const ull* t3u = (const ull*)t3;
    ull bias1 = ((const ull*)bb1)[lane];
    ull bias2 = ((const ull*)bb2)[lane];
    ull bias3 = ((const ull*)bb3)[lane];

    for (;;) {
        int atom;
        if (lane == 0) atom = atomicAdd(&g_ctr, 1);
        atom = __shfl_sync(0xffffffffu, atom, 0);
        if (atom >= n) break;

        int e0 = g_off[atom], e1 = g_off[atom + 1];
        Acc A = {0ull,0ull,0ull,0ull,0ull,0ull,0ull,0ull,0ull,0ull};

        if (e0 < e1) {
            int zi = z[atom];
            ull zS2 = ((const ull*)g_ZS)[zi * 32 + lane];

            int idx = e0;
            while (e1 - idx > 4) {
                int nb = e1 - idx; if (nb > 8) nb = 8;
                do_batch<8>(idx, e1, nb, lane, ei, nE, z, ew, evn, attr,
                            t1u, t2u, t3u, bias1, bias2, bias3, zS2, att2, meta, A);
                idx += 8;
            }
            if (e1 - idx > 0) {
                do_batch<4>(idx, e1, e1 - idx, lane, ei, nE, z, ew, evn, attr,
                            t1u, t2u, t3u, bias1, bias2, bias3, zS2, att2, meta, A);
            }
        }

        int base = atom * 64 + lane * 2;
        float2 vI = unpack2(A.I);
        g_accI[base] = vI.x; g_accI[base + 1] = vI.y;
        float2 vAx = unpack2(A.Ax), vAy = unpack2(A.Ay), vAz = unpack2(A.Az);
        int bA = base * 3;
        g_accA[bA + 0] = vAx.x; g_accA[bA + 1] = vAy.x; g_accA[bA + 2] = vAz.x;
        g_accA[bA + 3] = vAx.y; g_accA[bA + 4] = vAy.y; g_accA[bA + 5] = vAz.y;
        float2 vSxx = unpack2(A.Sxx), vSyy = unpack2(A.Syy), vSzz = unpack2(A.Szz);
        float2 vSxy = unpack2(A.Sxy), vSxz = unpack2(A.Sxz), vSyz = unpack2(A.Syz);
        int bS = base * 6;
        g_accS[bS + 0] = vSxx.x; g_accS[bS + 1] = vSyy.x; g_accS[bS + 2] = vSzz.x;
        g_accS[bS + 3] = vSxy.x; g_accS[bS + 4] = vSxz.x; g_accS[bS + 5] = vSyz.x;
        g_accS[bS + 6] = vSxx.y; g_accS[bS + 7] = vSyy.y; g_accS[bS + 8] = vSzz.y;
        g_accS[bS + 9] = vSxy.y; g_accS[bS + 10] = vSxz.y; g_accS[bS + 11] = vSyz.y;
    }
}

// ------------------------------------------------------------------
// tn -> layernorm -> MLP -> n0
// ------------------------------------------------------------------
__device__ __forceinline__ float sq(float x) { return x * x; }
__device__ __forceinline__ float silu(float x) { return x / (1.0f + expf(-x)); }

__global__ void k_mlp(const float* __restrict__ lng, const float* __restrict__ lnb,
                      const float* __restrict__ w1, const float* __restrict__ b1,
                      const float* __restrict__ w2, const float* __restrict__ b2,
                      int n)
{
    extern __shared__ float sm[];
    float* w1T  = sm;               // [j(64)][o(128)]
    float* w2nT = w1T + 64 * 128;   // [j(128)][h(64)]
    float* sb1  = w2nT + 128 * 64;
    float* sb2  = sb1 + 128;
    float* slg  = sb2 + 64;
    float* slb  = slg + 64;
    float* wk   = slb + 64;         // NW * 192

    int tid = threadIdx.x;
    for (int i = tid; i < 64 * 128; i += blockDim.x) {
        int j = i >> 7, o = i & 127;
        w1T[i] = w1[o * 64 + j];
    }
    for (int i = tid; i < 128 * 64; i += blockDim.x) {
        int j = i >> 6, h = i & 63;
        w2nT[i] = w2[h * 3 * 128 + j];
    }
    for (int i = tid; i < 128; i += blockDim.x) sb1[i] = b1[i];
    for (int i = tid; i < 64; i += blockDim.x) {
        sb2[i] = b2[3 * i]; slg[i] = lng[i]; slb[i] = lnb[i];
    }
    __syncthreads();

    int warp = tid >> 5, lane = tid & 31;
    float* nm = wk + warp * 192;
    float* h1 = nm + 64;
    const float2* w2n2 = (const float2*)w2nT;

    for (int atom = blockIdx.x * NW + warp; atom < n; atom += gridDim.x * NW) {
        int h0 = lane * 2;
        int base = atom * 64 + h0;
        float i0a = g_accI[base], i0b = g_accI[base + 1];
        const float* A = g_accA + base * 3;
        const float* S = g_accS + base * 6;
        float tna = sq(i0a + S[0]) + sq(i0a + S[1]) + sq(i0a + S[2])
                  + 2.0f * (sq(S[3]) + sq(S[4]) + sq(S[5]) + sq(A[0]) + sq(A[1]) + sq(A[2]));
        float tnb = sq(i0b + S[6]) + sq(i0b + S[7]) + sq(i0b + S[8])
                  + 2.0f * (sq(S[9]) + sq(S[10]) + sq(S[11]) + sq(A[3]) + sq(A[4]) + sq(A[5]));
        float s = tna + tnb;
        for (int o = 16; o; o >>= 1) s += __shfl_xor_sync(0xffffffffu, s, o);
        float mu = s * (1.0f / 64.0f);
        float da = tna - mu, db = tnb - mu;
        float vs = da * da + db * db;
        for (int o = 16; o; o >>= 1) vs += __shfl_xor_sync(0xffffffffu, vs, o);
        float inv = rsqrtf(vs * (1.0f / 64.0f) + 1e-5f);
        nm[h0]     = da * inv * slg[h0] + slb[h0];
        nm[h0 + 1] = db * inv * slg[h0 + 1] + slb[h0 + 1];
        __syncwarp();

        #pragma unroll
        for (int p = 0; p < 4; p++) {
            int o = lane + 32 * p;
            float acc = sb1[o];
            #pragma unroll 8
            for (int j = 0; j < 64; j++) acc = fmaf(w1T[j * 128 + o], nm[j], acc);
            h1[o] = silu(acc);
        }
        __syncwarp();

        float2 acc2 = ((const float2*)sb2)[lane];
        #pragma unroll 8
        for (int j = 0; j < 128; j++) {
            float hv = h1[j];
            float2 wv = w2n2[j * 32 + lane];
            acc2.x = fmaf(wv.x, hv, acc2.x);
            acc2.y = fmaf(wv.y, hv, acc2.y);
        }
        g_n0[base]     = silu(acc2.x);
        g_n0[base + 1] = silu(acc2.y);
        __syncwarp();
    }
}

// ------------------------------------------------------------------
// Final diagonal output
// ------------------------------------------------------------------
__global__ void k_final(const float* __restrict__ m0, const float* __restrict__ m1,
                        const float* __restrict__ m2, float* __restrict__ out, int n)
{
    __shared__ float m0T[64 * 64];
    __shared__ float msT[64 * 64];
    __shared__ float wk[NW][128];

    int tid = threadIdx.x;
    for (int i = tid; i < 64 * 64; i += blockDim.x) {
        int h = i >> 6, k = i & 63;
        m0T[i] = m0[k * 64 + h];
        msT[i] = m1[k * 64 + h] + m2[k * 64 + h];
    }
    __syncthreads();

    int warp = tid >> 5, lane = tid & 31;
    const float2* m0v = (const float2*)m0T;
    const float2* msv = (const float2*)msT;

    for (int atom = blockIdx.x * NW + warp; atom < n; atom += gridDim.x * NW) {
        int k0 = lane * 2;
        float2 n0v = ((const float2*)(g_n0 + atom * 64))[lane];
        float2 av  = ((const float2*)(g_accI + atom * 64))[lane];
        wk[warp][k0]     = av.x;
        wk[warp][k0 + 1] = av.y;
        __syncwarp();

        float2 d1 = {0.f, 0.f};
        #pragma unroll 8
        for (int h = 0; h < 64; h++) {
            float a = wk[warp][h];
            float2 m = m0v[h * 32 + lane];
            d1.x = fmaf(m.x, a, d1.x);
            d1.y = fmaf(m.y, a, d1.y);
        }
        d1.x *= n0v.x; d1.y *= n0v.y;
        wk[warp][64 + k0]     = d1.x;
        wk[warp][64 + k0 + 1] = d1.y;
        __syncwarp();

        float2 tt = {0.f, 0.f};
        #pragma unroll 8
        for (int h = 0; h < 64; h++) {
            float d = wk[warp][64 + h];
            float2 m = msv[h * 32 + lane];
            tt.x = fmaf(m.x, d, tt.x);
            tt.y = fmaf(m.y, d, tt.y);
        }
        float vx = d1.x + n0v.x * tt.x;
        float vy = d1.y + n0v.y * tt.y;

        float2* o = (float2*)(out + (size_t)(atom * 64 + k0) * 9);
        o[0] = make_float2(vx, 0.f);
        o[1] = make_float2(0.f, 0.f);
        o[2] = make_float2(vx, 0.f);
        o[3] = make_float2(0.f, 0.f);
        o[4] = make_float2(vx, vy);
        o[5] = make_float2(0.f, 0.f);
        o[6] = make_float2(0.f, vy);
        o[7] = make_float2(0.f, 0.f);
        o[8] = make_float2(0.f, vy);
        __syncwarp();
    }
}

// ------------------------------------------------------------------
extern "C" void kernel_launch(void* const* d_in, const int* in_sizes, int n_in,
                              void* d_out, int out_size)
{
    const int*   z    = (const int*)d_in[0];
    const int*   ei   = (const int*)d_in[1];
    const float* ew   = (const float*)d_in[2];
    const float* evn  = (const float*)d_in[3];
    const float* attr = (const float*)d_in[4];
    const float* emb  = (const float*)d_in[5];
    const float* e2w  = (const float*)d_in[6];
    const float* e2b  = (const float*)d_in[7];
    const float* d1w  = (const float*)d_in[8];
    const float* d1b  = (const float*)d_in[9];
    const float* d2w  = (const float*)d_in[10];
    const float* d2b  = (const float*)d_in[11];
    const float* d3w  = (const float*)d_in[12];
    const float* d3b  = (const float*)d_in[13];
    const float* lng  = (const float*)d_in[14];
    const float* lnb  = (const float*)d_in[15];
    const float* w1   = (const float*)d_in[16];
    const float* b1   = (const float*)d_in[17];
    const float* w2   = (const float*)d_in[18];
    const float* b2   = (const float*)d_in[19];
    const float* m0   = (const float*)d_in[20];
    const float* m1   = (const float*)d_in[21];
    const float* m2   = (const float*)d_in[22];
    float* out = (float*)d_out;

    int n    = in_sizes[0];
    int nE   = in_sizes[2];
    int maxz = in_sizes[5] / 64;
    if (maxz > 256) maxz = 256;

    size_t smemE = (size_t)(3 * 64 * 64 + 3 * 64 + NWE * 1184) * sizeof(float);
    size_t smemM = (size_t)(64 * 128 + 128 * 64 + 128 + 3 * 64 + NW * 192) * sizeof(float);
    cudaFuncSetAttribute(k_edge, cudaFuncAttributeMaxDynamicSharedMemorySize, (int)smemE);
    cudaFuncSetAttribute(k_mlp,  cudaFuncAttributeMaxDynamicSharedMemorySize, (int)smemM);

    k_zero<<<(n + 255) / 256, 256>>>(n);
    k_count<<<(nE + 255) / 256, 256>>>(ei, nE);
    k_pre<<<maxz, 64>>>(emb, e2w, e2b);
    k_scan<<<1, 1024>>>(n);
    k_scatter<<<(nE + 255) / 256, 256>>>(ei, nE);

    k_edge<<<152, NWE * 32, smemE>>>(z, ei, ew, evn, attr,
                                     d1w, d1b, d2w, d2b, d3w, d3b, n, nE);
    int ablocks = (n + NW - 1) / NW;
    k_mlp<<<ablocks, NW * 32, smemM>>>(lng, lnb, w1, b1, w2, b2, n);
    k_final<<<ablocks, NW * 32>>>(m0, m1, m2, out, n);
}

// round 4
// speedup vs baseline: 3.1259x; 1.3982x over previous
#include <cuda_runtime.h>
#include <math.h>

#define N_MAX 10000
#define E_MAX 160000
#define HD 64
#define NW 8
#define NWE 12
#define EB 8
#define RC_F 4.5f
#define PI_F 3.14159265358979323846f

typedef unsigned long long ull;

__device__ __forceinline__ ull fma2(ull a, ull b, ull c) {
    ull d; asm("fma.rn.f32x2 %0,%1,%2,%3;" : "=l"(d) : "l"(a), "l"(b), "l"(c)); return d;
}
__device__ __forceinline__ ull mul2(ull a, ull b) {
    ull d; asm("mul.rn.f32x2 %0,%1,%2;" : "=l"(d) : "l"(a), "l"(b)); return d;
}
__device__ __forceinline__ ull add2(ull a, ull b) {
    ull d; asm("add.rn.f32x2 %0,%1,%2;" : "=l"(d) : "l"(a), "l"(b)); return d;
}
__device__ __forceinline__ ull pack2(float x, float y) {
    ull d; asm("mov.b64 %0,{%1,%2};" : "=l"(d) : "f"(x), "f"(y)); return d;
}
__device__ __forceinline__ ull packdup(float x) {
    ull d; asm("mov.b64 %0,{%1,%1};" : "=l"(d) : "f"(x)); return d;
}
__device__ __forceinline__ float2 unpack2(ull a) {
    float2 v; asm("mov.b64 {%0,%1},%2;" : "=f"(v.x), "=f"(v.y) : "l"(a)); return v;
}

// ---- device scratch ----
__device__ int   g_cnt[N_MAX];
__device__ int   g_off[N_MAX + 1];
__device__ int   g_perm[E_MAX];
__device__ int   g_ctr;
__device__ float g_ZS[256 * 64];
__device__ float g_ZD[256 * 64];
__device__ float g_accI[N_MAX * HD];
__device__ float g_accA[N_MAX * HD * 3];
__device__ float g_accS[N_MAX * HD * 6];

// ------------------------------------------------------------------
// Counting sort of edges by src
// ------------------------------------------------------------------
__global__ void k_zero(int n) {
    int i = blockIdx.x * blockDim.x + threadIdx.x;
    if (i == 0) g_ctr = 0;
    if (i < n) g_cnt[i] = 0;
}

__global__ void k_count(const int* __restrict__ ei, int nE) {
    int e = blockIdx.x * blockDim.x + threadIdx.x;
    if (e < nE) atomicAdd(&g_cnt[ei[e]], 1);
}

__global__ void k_scan(int n) {
    __shared__ int part[1024];
    int tid = threadIdx.x;
    const int CH = 16;
    int beg = tid * CH;
    int loc[CH];
    int s = 0;
    if (beg + CH <= n) {
        int4 a0 = *(const int4*)&g_cnt[beg];
        int4 a1 = *(const int4*)&g_cnt[beg + 4];
        int4 a2 = *(const int4*)&g_cnt[beg + 8];
        int4 a3 = *(const int4*)&g_cnt[beg + 12];
        int v[CH] = {a0.x,a0.y,a0.z,a0.w, a1.x,a1.y,a1.z,a1.w,
                     a2.x,a2.y,a2.z,a2.w, a3.x,a3.y,a3.z,a3.w};
        #pragma unroll
        for (int i = 0; i < CH; i++) { loc[i] = s; s += v[i]; }
    } else {
        #pragma unroll
        for (int i = 0; i < CH; i++) {
            loc[i] = s;
            int idx = beg + i;
            if (idx < n) s += g_cnt[idx];
        }
    }
    part[tid] = s;
    __syncthreads();
    for (int off = 1; off < 1024; off <<= 1) {
        int t = 0;
        if (tid >= off) t = part[tid - off];
        __syncthreads();
        part[tid] += t;
        __syncthreads();
    }
    int excl = part[tid] - s;
    #pragma unroll
    for (int i = 0; i < CH; i++) {
        int idx = beg + i;
        if (idx < n) { g_off[idx] = excl + loc[i]; g_cnt[idx] = 0; }
    }
    if (tid == 1023) g_off[n] = part[1023];
}

__global__ void k_scatter(const int* __restrict__ ei, int nE) {
    int e = blockIdx.x * blockDim.x + threadIdx.x;
    if (e < nE) {
        int s = ei[e];
        int pos = g_off[s] + atomicAdd(&g_cnt[s], 1);
        g_perm[pos] = e;
    }
}

// ------------------------------------------------------------------
// Precompute ZS/ZD tables over distinct z values
// ------------------------------------------------------------------
__global__ void k_pre(const float* __restrict__ emb, const float* __restrict__ e2w,
                      const float* __restrict__ e2b) {
    int zz = blockIdx.x;
    int h = threadIdx.x;
    __shared__ float er[64];
    er[h] = emb[zz * 64 + h];
    __syncthreads();
    float ss = e2b[h], sd = 0.f;
    #pragma unroll 8
    for (int j = 0; j < 64; j++) {
        ss = fmaf(e2w[h * 128 + j], er[j], ss);
        sd = fmaf(e2w[h * 128 + 64 + j], er[j], sd);
    }
    g_ZS[zz * 64 + h] = ss;
    g_ZD[zz * 64 + h] = sd;
}

// ------------------------------------------------------------------
// Edge kernel: warp/atom, 8-edge batches, prefetch pipeline, f32x2.
// ------------------------------------------------------------------
struct Pref {
    ull zd[EB];
    float2 ar[EB];
    float mw, mx, my, mz;   // valid on lanes < EB
};

__device__ __forceinline__ void prefetch(int idx, int e1, int lane,
        const int* __restrict__ ei, int nE, const int* __restrict__ z,
        const float* __restrict__ ew, const float* __restrict__ evn,
        const float* __restrict__ attr, Pref& P)
{
    int eidx[EB];
    #pragma unroll
    for (int b = 0; b < EB; b++) {
        int ii = idx + b; if (ii >= e1) ii = e1 - 1;
        eidx[b] = g_perm[ii];
    }
    int dst[EB];
    #pragma unroll
    for (int b = 0; b < EB; b++) dst[b] = ei[nE + eidx[b]];
    int zj[EB];
    #pragma unroll
    for (int b = 0; b < EB; b++) zj[b] = z[dst[b]];
    #pragma unroll
    for (int b = 0; b < EB; b++)
        P.zd[b] = ((const ull*)g_ZD)[zj[b] * 32 + lane];
    #pragma unroll
    for (int b = 0; b < EB; b++)
        P.ar[b] = ((const float2*)attr)[(size_t)eidx[b] * 32 + lane];
    if (lane < EB) {
        int ii = idx + lane; if (ii >= e1) ii = e1 - 1;
        int e = g_perm[ii];
        P.mw = ew[e];
        P.mx = evn[3 * e + 0];
        P.my = evn[3 * e + 1];
        P.mz = evn[3 * e + 2];
    }
}

__device__ __forceinline__ void stage(const Pref& P, int lane, ull* attw, ull* meta)
{
    #pragma unroll
    for (int b = 0; b < EB; b++) {
        attw[b * 64 + 2 * lane]     = pack2(P.ar[b].x, P.ar[b].x);
        attw[b * 64 + 2 * lane + 1] = pack2(P.ar[b].y, P.ar[b].y);
    }
    if (lane < EB) {
        float w = P.mw;
        float C = (w < RC_F) ? 0.5f * (cosf(w * (PI_F / RC_F)) + 1.0f) : 0.0f;
        float vx = P.mx, vy = P.my, vz = P.mz;
        float tr3 = (vx * vx + vy * vy + vz * vz) * (1.0f / 3.0f);
        ull* mp = meta + lane * 10;
        mp[0] = packdup(C);
        mp[1] = packdup(vx); mp[2] = packdup(vy); mp[3] = packdup(vz);
        mp[4] = packdup(vx * vx - tr3);
        mp[5] = packdup(vy * vy - tr3);
        mp[6] = packdup(vz * vz - tr3);
        mp[7] = packdup(vx * vy); mp[8] = packdup(vx * vz); mp[9] = packdup(vy * vz);
    }
}

struct Acc { ull I, Ax, Ay, Az, Sxx, Syy, Szz, Sxy, Sxz, Syz; };

__global__ __launch_bounds__(NWE * 32, 1)
void k_edge(const int* __restrict__ z,
            const int* __restrict__ ei,
            const float* __restrict__ ew,
            const float* __restrict__ evn,
            const float* __restrict__ attr,
            const float* __restrict__ d1w, const float* __restrict__ d1b,
            const float* __restrict__ d2w, const float* __restrict__ d2b,
            const float* __restrict__ d3w, const float* __restrict__ d3b,
            int n, int nE)
{
    extern __shared__ float sm[];
    float* t1f = sm;                       // 4096
    float* t2f = t1f + 4096;
    float* t3f = t2f + 4096;
    float* bbf = t3f + 4096;               // 192
    float* attf = bbf + 192;               // NWE * 2048
    float* metaf = attf + NWE * 2048;      // NWE * 160

    int tid = threadIdx.x;
    // interleaved weight layout: float4 at (j2*32+l) = (t[j0][h0], t[j0][h1], t[j1][h0], t[j1][h1])
    for (int i = tid; i < 1024; i += blockDim.x) {
        int j2 = i >> 5, l = i & 31;
        int j0 = 2 * j2, j1 = j0 + 1, h0 = 2 * l, h1 = h0 + 1;
        int base = i * 4;
        t1f[base + 0] = d1w[h0 * 64 + j0]; t1f[base + 1] = d1w[h1 * 64 + j0];
        t1f[base + 2] = d1w[h0 * 64 + j1]; t1f[base + 3] = d1w[h1 * 64 + j1];
        t2f[base + 0] = d2w[h0 * 64 + j0]; t2f[base + 1] = d2w[h1 * 64 + j0];
        t2f[base + 2] = d2w[h0 * 64 + j1]; t2f[base + 3] = d2w[h1 * 64 + j1];
        t3f[base + 0] = d3w[h0 * 64 + j0]; t3f[base + 1] = d3w[h1 * 64 + j0];
        t3f[base + 2] = d3w[h0 * 64 + j1]; t3f[base + 3] = d3w[h1 * 64 + j1];
    }
    for (int i = tid; i < 64; i += blockDim.x) {
        bbf[i] = d1b[i]; bbf[64 + i] = d2b[i]; bbf[128 + i] = d3b[i];
    }
    __syncthreads();

    int warp = tid >> 5, lane = tid & 31;
    const ulonglong2* t1q = (const ulonglong2*)t1f;
    const ulonglong2* t2q = (const ulonglong2*)t2f;
    const ulonglong2* t3q = (const ulonglong2*)t3f;
    ull* attw0 = (ull*)(attf + warp * 2048);
    ull* attw1 = attw0 + 512;
    ull* meta  = (ull*)(metaf + warp * 160);

    ull bias1 = ((const ull*)bbf)[lane];
    ull bias2 = ((const ull*)(bbf + 64))[lane];
    ull bias3 = ((const ull*)(bbf + 128))[lane];

    for (;;) {
        int atom;
        if (lane == 0) atom = atomicAdd(&g_ctr, 1);
        atom = __shfl_sync(0xffffffffu, atom, 0);
        if (atom >= n) break;

        int e0 = g_off[atom], e1 = g_off[atom + 1];
        Acc A = {0ull,0ull,0ull,0ull,0ull,0ull,0ull,0ull,0ull,0ull};

        if (e0 < e1) {
            ull zS2 = ((const ull*)g_ZS)[z[atom] * 32 + lane];
            Pref P;
            prefetch(e0, e1, lane, ei, nE, z, ew, evn, attr, P);
            int buf = 0;

            for (int idx = e0; idx < e1; idx += EB) {
                ull* attw = buf ? attw1 : attw0;
                stage(P, lane, attw, meta);
                ull zdc[EB];
                #pragma unroll
                for (int b = 0; b < EB; b++) zdc[b] = P.zd[b];
                __syncwarp();

                if (idx + EB < e1)
                    prefetch(idx + EB, e1, lane, ei, nE, z, ew, evn, attr, P);

                ull s1[EB], s2[EB], s3[EB];
                #pragma unroll
                for (int b = 0; b < EB; b++) { s1[b] = bias1; s2[b] = bias2; s3[b] = bias3; }

                const ulonglong2* attq = (const ulonglong2*)attw;
                #pragma unroll 4
                for (int j2 = 0; j2 < 32; j2++) {
                    ulonglong2 q1 = t1q[j2 * 32 + lane];
                    ulonglong2 q2 = t2q[j2 * 32 + lane];
                    ulonglong2 q3 = t3q[j2 * 32 + lane];
                    #pragma unroll
                    for (int b = 0; b < EB; b++) {
                        ulonglong2 aa = attq[b * 32 + j2];
                        s1[b] = fma2(q1.x, aa.x, s1[b]);
                        s2[b] = fma2(q2.x, aa.x, s2[b]);
                        s3[b] = fma2(q3.x, aa.x, s3[b]);
                        s1[b] = fma2(q1.y, aa.y, s1[b]);
                        s2[b] = fma2(q2.y, aa.y, s2[b]);
                        s3[b] = fma2(q3.y, aa.y, s3[b]);
                    }
                }

                int nb = e1 - idx; if (nb > EB) nb = EB;
                #pragma unroll
                for (int b = 0; b < EB; b++) {
                    if (b >= nb) break;
                    const ull* mp = meta + b * 10;
                    ull zfac = mul2(mp[0], add2(zS2, zdc[b]));
                    ull g1 = mul2(s1[b], zfac);
                    ull g2 = mul2(s2[b], zfac);
                    ull g3 = mul2(s3[b], zfac);
                    A.I   = add2(A.I, g1);
                    A.Ax  = fma2(g2, mp[1], A.Ax);
                    A.Ay  = fma2(g2, mp[2], A.Ay);
                    A.Az  = fma2(g2, mp[3], A.Az);
                    A.Sxx = fma2(g3, mp[4], A.Sxx);
                    A.Syy = fma2(g3, mp[5], A.Syy);
                    A.Szz = fma2(g3, mp[6], A.Szz);
                    A.Sxy = fma2(g3, mp[7], A.Sxy);
                    A.Sxz = fma2(g3, mp[8], A.Sxz);
                    A.Syz = fma2(g3, mp[9], A.Syz);
                }
                buf ^= 1;
                __syncwarp();
            }
        }

        int base = atom * 64 + lane * 2;
        float2 vI = unpack2(A.I);
        g_accI[base] = vI.x; g_accI[base + 1] = vI.y;
        float2 vAx = unpack2(A.Ax), vAy = unpack2(A.Ay), vAz = unpack2(A.Az);
        int bA = base * 3;
        g_accA[bA + 0] = vAx.x; g_accA[bA + 1] = vAy.x; g_accA[bA + 2] = vAz.x;
        g_accA[bA + 3] = vAx.y; g_accA[bA + 4] = vAy.y; g_accA[bA + 5] = vAz.y;
        float2 vSxx = unpack2(A.Sxx), vSyy = unpack2(A.Syy), vSzz = unpack2(A.Szz);
        float2 vSxy = unpack2(A.Sxy), vSxz = unpack2(A.Sxz), vSyz = unpack2(A.Syz);
        int bS = base * 6;
        g_accS[bS + 0] = vSxx.x; g_accS[bS + 1] = vSyy.x; g_accS[bS + 2] = vSzz.x;
        g_accS[bS + 3] = vSxy.x; g_accS[bS + 4] = vSxz.x; g_accS[bS + 5] = vSyz.x;
        g_accS[bS + 6] = vSxx.y; g_accS[bS + 7] = vSyy.y; g_accS[bS + 8] = vSzz.y;
        g_accS[bS + 9] = vSxy.y; g_accS[bS + 10] = vSxz.y; g_accS[bS + 11] = vSyz.y;
    }
}

// ------------------------------------------------------------------
// Post: tn -> LN -> MLP -> n0 -> diagonal output (merged)
// ------------------------------------------------------------------
__device__ __forceinline__ float sq(float x) { return x * x; }
__device__ __forceinline__ float silu(float x) { return x / (1.0f + expf(-x)); }

__global__ void k_post(const float* __restrict__ lng, const float* __restrict__ lnb,
                       const float* __restrict__ w1, const float* __restrict__ b1,
                       const float* __restrict__ w2, const float* __restrict__ b2,
                       const float* __restrict__ m0, const float* __restrict__ m1,
                       const float* __restrict__ m2, float* __restrict__ out, int n)
{
    extern __shared__ float sm[];
    float* w1T  = sm;               // [j(64)][o(128)]
    float* w2nT = w1T + 64 * 128;   // [j(128)][h(64)]
    float* m0T  = w2nT + 128 * 64;  // [h][k]
    float* msT  = m0T + 64 * 64;    // [h][k] of m1+m2
    float* sb1  = msT + 64 * 64;    // 128
    float* sb2  = sb1 + 128;        // 64
    float* slg  = sb2 + 64;
    float* slb  = slg + 64;
    float* wk   = slb + 64;         // NW * 320

    int tid = threadIdx.x;
    for (int i = tid; i < 64 * 128; i += blockDim.x) {
        int j = i >> 7, o = i & 127;
        w1T[i] = w1[o * 64 + j];
    }
    for (int i = tid; i < 128 * 64; i += blockDim.x) {
        int j = i >> 6, h = i & 63;
        w2nT[i] = w2[h * 3 * 128 + j];
    }
    for (int i = tid; i < 64 * 64; i += blockDim.x) {
        int h = i >> 6, k = i & 63;
        m0T[i] = m0[k * 64 + h];
        msT[i] = m1[k * 64 + h] + m2[k * 64 + h];
    }
    for (int i = tid; i < 128; i += blockDim.x) sb1[i] = b1[i];
    for (int i = tid; i < 64; i += blockDim.x) {
        sb2[i] = b2[3 * i]; slg[i] = lng[i]; slb[i] = lnb[i];
    }
    __syncthreads();

    int warp = tid >> 5, lane = tid & 31;
    float* nm  = wk + warp * 320;   // 64
    float* h1  = nm + 64;           // 128
    float* wkv = h1 + 128;          // 128
    const float2* w2n2 = (const float2*)w2nT;
    const float2* m0v  = (const float2*)m0T;
    const float2* msv  = (const float2*)msT;

    for (int atom = blockIdx.x * NW + warp; atom < n; atom += gridDim.x * NW) {
        int h0 = lane * 2;
        int base = atom * 64 + h0;
        float i0a = g_accI[base], i0b = g_accI[base + 1];
        const float* Ap = g_accA + base * 3;
        const float* Sp = g_accS + base * 6;
        float tna = sq(i0a + Sp[0]) + sq(i0a + Sp[1]) + sq(i0a + Sp[2])
                  + 2.0f * (sq(Sp[3]) + sq(Sp[4]) + sq(Sp[5]) + sq(Ap[0]) + sq(Ap[1]) + sq(Ap[2]));
        float tnb = sq(i0b + Sp[6]) + sq(i0b + Sp[7]) + sq(i0b + Sp[8])
                  + 2.0f * (sq(Sp[9]) + sq(Sp[10]) + sq(Sp[11]) + sq(Ap[3]) + sq(Ap[4]) + sq(Ap[5]));
        // stash accI for the final GEMV
        wkv[h0] = i0a; wkv[h0 + 1] = i0b;

        float s = tna + tnb;
        for (int o = 16; o; o >>= 1) s += __shfl_xor_sync(0xffffffffu, s, o);
        float mu = s * (1.0f / 64.0f);
        float da = tna - mu, db = tnb - mu;
        float vs = da * da + db * db;
        for (int o = 16; o; o >>= 1) vs += __shfl_xor_sync(0xffffffffu, vs, o);
        float inv = rsqrtf(vs * (1.0f / 64.0f) + 1e-5f);
        nm[h0]     = da * inv * slg[h0] + slb[h0];
        nm[h0 + 1] = db * inv * slg[h0 + 1] + slb[h0 + 1];
        __syncwarp();

        #pragma unroll
        for (int p = 0; p < 4; p++) {
            int o = lane + 32 * p;
            float acc = sb1[o];
            #pragma unroll 8
            for (int j = 0; j < 64; j++) acc = fmaf(w1T[j * 128 + o], nm[j], acc);
            h1[o] = silu(acc);
        }
        __syncwarp();

        float2 acc2 = ((const float2*)sb2)[lane];
        #pragma unroll 8
        for (int j = 0; j < 128; j++) {
            float hv = h1[j];
            float2 wv = w2n2[j * 32 + lane];
            acc2.x = fmaf(wv.x, hv, acc2.x);
            acc2.y = fmaf(wv.y, hv, acc2.y);
        }
        float n0x = silu(acc2.x), n0y = silu(acc2.y);

        // d1[k] = n0[k] * sum_h m0T[h][k] * accI[h]
        float2 d1 = {0.f, 0.f};
        #pragma unroll 8
        for (int h = 0; h < 64; h++) {
            float a = wkv[h];
            float2 m = m0v[h * 32 + lane];
            d1.x = fmaf(m.x, a, d1.x);
            d1.y = fmaf(m.y, a, d1.y);
        }
        d1.x *= n0x; d1.y *= n0y;
        __syncwarp();
        wkv[h0] = d1.x; wkv[h0 + 1] = d1.y;
        __syncwarp();

        float2 tt = {0.f, 0.f};
        #pragma unroll 8
        for (int h = 0; h < 64; h++) {
            float d = wkv[h];
            float2 m = msv[h * 32 + lane];
            tt.x = fmaf(m.x, d, tt.x);
            tt.y = fmaf(m.y, d, tt.y);
        }
        float vx = d1.x + n0x * tt.x;
        float vy = d1.y + n0y * tt.y;

        float2* o = (float2*)(out + (size_t)(atom * 64 + h0) * 9);
        o[0] = make_float2(vx, 0.f);
        o[1] = make_float2(0.f, 0.f);
        o[2] = make_float2(vx, 0.f);
        o[3] = make_float2(0.f, 0.f);
        o[4] = make_float2(vx, vy);
        o[5] = make_float2(0.f, 0.f);
        o[6] = make_float2(0.f, vy);
        o[7] = make_float2(0.f, 0.f);
        o[8] = make_float2(0.f, vy);
        __syncwarp();
    }
}

// ------------------------------------------------------------------
extern "C" void kernel_launch(void* const* d_in, const int* in_sizes, int n_in,
                              void* d_out, int out_size)
{
    const int*   z    = (const int*)d_in[0];
    const int*   ei   = (const int*)d_in[1];
    const float* ew   = (const float*)d_in[2];
    const float* evn  = (const float*)d_in[3];
    const float* attr = (const float*)d_in[4];
    const float* emb  = (const float*)d_in[5];
    const float* e2w  = (const float*)d_in[6];
    const float* e2b  = (const float*)d_in[7];
    const float* d1w  = (const float*)d_in[8];
    const float* d1b  = (const float*)d_in[9];
    const float* d2w  = (const float*)d_in[10];
    const float* d2b  = (const float*)d_in[11];
    const float* d3w  = (const float*)d_in[12];
    const float* d3b  = (const float*)d_in[13];
    const float* lng  = (const float*)d_in[14];
    const float* lnb  = (const float*)d_in[15];
    const float* w1   = (const float*)d_in[16];
    const float* b1   = (const float*)d_in[17];
    const float* w2   = (const float*)d_in[18];
    const float* b2   = (const float*)d_in[19];
    const float* m0   = (const float*)d_in[20];
    const float* m1   = (const float*)d_in[21];
    const float* m2   = (const float*)d_in[22];
    float* out = (float*)d_out;

    int n    = in_sizes[0];
    int nE   = in_sizes[2];
    int maxz = in_sizes[5] / 64;
    if (maxz > 256) maxz = 256;

    size_t smemE = (size_t)(3 * 4096 + 192 + NWE * 2048 + NWE * 160) * sizeof(float);
    size_t smemP = (size_t)(64 * 128 + 128 * 64 + 2 * 64 * 64 + 128 + 3 * 64 + NW * 320) * sizeof(float);
    cudaFuncSetAttribute(k_edge, cudaFuncAttributeMaxDynamicSharedMemorySize, (int)smemE);
    cudaFuncSetAttribute(k_post, cudaFuncAttributeMaxDynamicSharedMemorySize, (int)smemP);

    k_zero<<<(n + 255) / 256, 256>>>(n);
    k_count<<<(nE + 255) / 256, 256>>>(ei, nE);
    k_pre<<<maxz, 64>>>(emb, e2w, e2b);
    k_scan<<<1, 1024>>>(n);
    k_scatter<<<(nE + 255) / 256, 256>>>(ei, nE);

    k_edge<<<152, NWE * 32, smemE>>>(z, ei, ew, evn, attr,
                                     d1w, d1b, d2w, d2b, d3w, d3b, n, nE);
    k_post<<<304, NW * 32, smemP>>>(lng, lnb, w1, b1, w2, b2, m0, m1, m2, out, n);
}